// round 1
// baseline (speedup 1.0000x reference)
#include <cuda_runtime.h>
#include <climits>

#define Bc 4
#define Fc 60082
#define Cc 14695
#define Dc 256
#define KNc 64
#define KHc 128

// Scratch (no allocation allowed) — __device__ globals.
__device__ float g_u[Dc];        // W_proj @ w_ff
__device__ float g_w2v[Dc/2];    // W2 @ w_ff
__device__ float g_comp[Bc];     // company_mem . w_fc + b_fc
__device__ float g_c0;           // b_proj . w_ff
__device__ float g_c2;           // b2 . w_ff
__device__ float g_hisdot[Bc*KHc]; // h(f) . w_ff - c2 per his slot (includes c2 actually)

__device__ __forceinline__ float warp_sum(float v) {
    v += __shfl_xor_sync(0xffffffffu, v, 16);
    v += __shfl_xor_sync(0xffffffffu, v, 8);
    v += __shfl_xor_sync(0xffffffffu, v, 4);
    v += __shfl_xor_sync(0xffffffffu, v, 2);
    v += __shfl_xor_sync(0xffffffffu, v, 1);
    return v; // all lanes hold full sum (butterfly)
}

// 8-float dot, both pointers 16B-aligned.
__device__ __forceinline__ float dot8(const float* __restrict__ a, const float* __restrict__ b) {
    float4 a0 = ((const float4*)a)[0], a1 = ((const float4*)a)[1];
    float4 b0 = ((const float4*)b)[0], b1 = ((const float4*)b)[1];
    return a0.x*b0.x + a0.y*b0.y + a0.z*b0.z + a0.w*b0.w
         + a1.x*b1.x + a1.y*b1.y + a1.z*b1.z + a1.w*b1.w;
}

// ---------------------------------------------------------------------------
// Kernel 1: tiny precomputations. One warp per task.
//   tasks 0..255      : u[k]   = W_proj[k,:] . w_ff
//   tasks 256..383    : w2v[j] = W2[j,:] . w_ff
//   tasks 384..387    : comp[b]
//   task 388          : c0 = b_proj . w_ff
//   task 389          : c2 = b2 . w_ff
// ---------------------------------------------------------------------------
__global__ void prep_kernel(const float* __restrict__ company_emb,
                            const float* __restrict__ comp_table,
                            const float* __restrict__ W_proj,
                            const float* __restrict__ b_proj,
                            const float* __restrict__ theta,
                            const float* __restrict__ w_ff,
                            const float* __restrict__ w_fc,
                            const float* __restrict__ b_fc,
                            const float* __restrict__ W2,
                            const float* __restrict__ b2,
                            const int*   __restrict__ com_id)
{
    int wt   = (blockIdx.x * blockDim.x + threadIdx.x) >> 5;
    int lane = threadIdx.x & 31;

    if (wt < Dc) {
        float s = warp_sum(dot8(W_proj + (size_t)wt*Dc + lane*8, w_ff + lane*8));
        if (lane == 0) g_u[wt] = s;
    } else if (wt < Dc + Dc/2) {
        int j = wt - Dc;
        float s = warp_sum(dot8(W2 + (size_t)j*Dc + lane*8, w_ff + lane*8));
        if (lane == 0) g_w2v[j] = s;
    } else if (wt < Dc + Dc/2 + Bc) {
        int b   = wt - Dc - Dc/2;
        int cid = com_id[b];
        float th = theta[cid];
        float s = 0.f;
        #pragma unroll
        for (int i = 0; i < 8; i++) {
            int d = lane*8 + i;
            float m = (1.f - th) * company_emb[b*Dc + d] + th * comp_table[(size_t)cid*Dc + d];
            s += m * w_fc[d];
        }
        s = warp_sum(s);
        if (lane == 0) g_comp[b] = s + b_fc[0];
    } else if (wt == Dc + Dc/2 + Bc) {
        float s = warp_sum(dot8(b_proj + lane*8, w_ff + lane*8));
        if (lane == 0) g_c0 = s;
    } else if (wt == Dc + Dc/2 + Bc + 1) {
        float s = warp_sum(dot8(b2 + lane*8, w_ff + lane*8));
        if (lane == 0) g_c2 = s;
    }
}

// ---------------------------------------------------------------------------
// Kernel 2: his-node MLP collapsed to a scalar per his slot.
//   hisdot[i] = leaky(rfe[f] @ W1 + b1) . w2v + c2,  f = his_nodes[i]
// One block (128 threads, thread j owns hidden unit j) per his slot.
// ---------------------------------------------------------------------------
__global__ void his_kernel(const float* __restrict__ raw_field_embed,
                           const float* __restrict__ W1,
                           const float* __restrict__ b1,
                           const int*   __restrict__ his_nodes)
{
    __shared__ __align__(16) float rfe[Dc];
    __shared__ float red[4];
    int f = his_nodes[blockIdx.x];
    int t = threadIdx.x; // 0..127
    rfe[t]       = raw_field_embed[(size_t)f*Dc + t];
    rfe[t + 128] = raw_field_embed[(size_t)f*Dc + t + 128];
    __syncthreads();

    float acc = b1[t];
    #pragma unroll 8
    for (int k = 0; k < Dc; k++)
        acc += rfe[k] * W1[(size_t)k*(Dc/2) + t];   // coalesced across t
    float y = (acc >= 0.f) ? acc : 0.01f * acc;
    float p = y * g_w2v[t];

    p = warp_sum(p);
    if ((t & 31) == 0) red[t >> 5] = p;
    __syncthreads();
    if (t == 0)
        g_hisdot[blockIdx.x] = red[0] + red[1] + red[2] + red[3] + g_c2;
}

// ---------------------------------------------------------------------------
// Kernel 3: dense pass (the only big one — streams field_table once).
//   out[b,f] = field_table[f] . u + c0 + b_ff + comp[b]
// One warp per field row; lanes 0..3 write the 4 batch rows.
// ---------------------------------------------------------------------------
__global__ void __launch_bounds__(256) main_kernel(const float* __restrict__ field_table,
                                                   const float* __restrict__ b_ff,
                                                   float* __restrict__ out)
{
    __shared__ __align__(16) float u_s[Dc];
    __shared__ float add_s[Bc];
    int t = threadIdx.x;
    u_s[t] = g_u[t];
    if (t < Bc) add_s[t] = g_comp[t] + b_ff[0] + g_c0;
    __syncthreads();

    int warp = t >> 5, lane = t & 31;
    int f = blockIdx.x * 8 + warp;
    if (f >= Fc) return;

    float s = dot8(field_table + (size_t)f*Dc + lane*8, u_s + lane*8);
    s = warp_sum(s); // all lanes have it
    if (lane < Bc) out[(size_t)lane*Fc + f] = s + add_s[lane];
}

// ---------------------------------------------------------------------------
// Kernel 4: sparse corrections. One block per batch; one warp per touched node.
// Overwrites the <=192 touched rows with the full value (set semantics).
// ---------------------------------------------------------------------------
__global__ void corr_kernel(const float* __restrict__ field_table,
                            const float* __restrict__ field_emb,
                            const float* __restrict__ alpha_fields,
                            const float* __restrict__ w_ff,
                            const float* __restrict__ b_ff,
                            const int*   __restrict__ now_nodes,
                            const int*   __restrict__ his_nodes,
                            float* __restrict__ out)
{
    __shared__ __align__(16) float u_s[Dc];
    __shared__ __align__(16) float wff_s[Dc];
    __shared__ int now_s[KNc], his_s[KHc];
    int b = blockIdx.x;
    int t = threadIdx.x; // 256
    u_s[t]   = g_u[t];
    wff_s[t] = w_ff[t];
    if (t < KNc) now_s[t] = now_nodes[b*KNc + t];
    if (t < KHc) his_s[t] = his_nodes[b*KHc + t];
    __syncthreads();

    float cb = g_comp[b] + b_ff[0];
    float c0 = g_c0;
    int warp = t >> 5, lane = t & 31;

    for (int node = warp; node < KNc + KHc; node += 8) {
        int f = (node < KNc) ? now_s[node] : his_s[node - KNc];

        float a1 = dot8(field_table + (size_t)f*Dc + lane*8, u_s  + lane*8);
        float a2 = dot8(field_emb   + (size_t)f*Dc + lane*8, wff_s + lane*8);
        a1 = warp_sum(a1);   // base_dot (without c0)
        a2 = warp_sum(a2);   // now term dot

        // membership: now (64 entries, 2/lane)
        bool inNow = (now_s[lane] == f) || (now_s[lane + 32] == f);
        unsigned mN = __ballot_sync(0xffffffffu, inNow);

        // membership + first matching slot in his (128 entries, 4/lane)
        int jmin = INT_MAX;
        #pragma unroll
        for (int r = 0; r < 4; r++) {
            int j = lane + r*32;
            if (his_s[j] == f && j < jmin) jmin = j;
        }
        #pragma unroll
        for (int o = 16; o > 0; o >>= 1) {
            int oth = __shfl_xor_sync(0xffffffffu, jmin, o);
            jmin = min(jmin, oth);
        }

        float alpha = alpha_fields[f];
        float val = (1.f - alpha) * (a1 + c0) + cb;
        if (mN)              val += alpha * a2;
        if (jmin != INT_MAX) val += alpha * g_hisdot[b*KHc + jmin];

        if (lane == 0) out[(size_t)b*Fc + f] = val; // duplicates write identical bits
    }
}

// ---------------------------------------------------------------------------
extern "C" void kernel_launch(void* const* d_in, const int* in_sizes, int n_in,
                              void* d_out, int out_size)
{
    const float* company_emb     = (const float*)d_in[0];
    const float* field_emb       = (const float*)d_in[1];
    const float* raw_field_embed = (const float*)d_in[2];
    const float* comp_table      = (const float*)d_in[3];
    const float* field_table     = (const float*)d_in[4];
    const float* W_proj          = (const float*)d_in[5];
    const float* b_proj          = (const float*)d_in[6];
    const float* theta           = (const float*)d_in[7];
    const float* alpha_fields    = (const float*)d_in[8];
    const float* w_ff            = (const float*)d_in[9];
    const float* b_ff            = (const float*)d_in[10];
    const float* w_fc            = (const float*)d_in[11];
    const float* b_fc            = (const float*)d_in[12];
    const float* W1              = (const float*)d_in[13];
    const float* b1              = (const float*)d_in[14];
    const float* W2              = (const float*)d_in[15];
    const float* b2              = (const float*)d_in[16];
    const int*   now_nodes       = (const int*)d_in[17];
    const int*   his_nodes       = (const int*)d_in[18];
    const int*   com_id          = (const int*)d_in[19];
    float* out = (float*)d_out;

    // 390 warp-tasks -> 49 blocks of 8 warps
    prep_kernel<<<49, 256>>>(company_emb, comp_table, W_proj, b_proj, theta,
                             w_ff, w_fc, b_fc, W2, b2, com_id);
    his_kernel<<<Bc*KHc, 128>>>(raw_field_embed, W1, b1, his_nodes);
    main_kernel<<<(Fc + 7) / 8, 256>>>(field_table, b_ff, out);
    corr_kernel<<<Bc, 256>>>(field_table, field_emb, alpha_fields, w_ff, b_ff,
                             now_nodes, his_nodes, out);
}

// round 2
// speedup vs baseline: 1.5536x; 1.5536x over previous
#include <cuda_runtime.h>
#include <climits>

#define Bc 4
#define Fc 60082
#define Cc 14695
#define Dc 256
#define KNc 64
#define KHc 128

// Scratch (no allocation allowed) — __device__ globals.
__device__ float g_u[Dc];        // W_proj @ w_ff
__device__ float g_w2v[Dc/2];    // W2 @ w_ff
__device__ float g_comp[Bc];     // company_mem . w_fc + b_fc
__device__ float g_c0;           // b_proj . w_ff
__device__ float g_c2;           // b2 . w_ff
__device__ float g_hisdot[Bc*KHc]; // leaky(rfe@W1+b1).w2v + c2 per his slot

__device__ __forceinline__ float warp_sum(float v) {
    v += __shfl_xor_sync(0xffffffffu, v, 16);
    v += __shfl_xor_sync(0xffffffffu, v, 8);
    v += __shfl_xor_sync(0xffffffffu, v, 4);
    v += __shfl_xor_sync(0xffffffffu, v, 2);
    v += __shfl_xor_sync(0xffffffffu, v, 1);
    return v; // all lanes hold full sum (butterfly)
}

// 8-float dot, both pointers 16B-aligned.
__device__ __forceinline__ float dot8(const float* __restrict__ a, const float* __restrict__ b) {
    float4 a0 = ((const float4*)a)[0], a1 = ((const float4*)a)[1];
    float4 b0 = ((const float4*)b)[0], b1 = ((const float4*)b)[1];
    return a0.x*b0.x + a0.y*b0.y + a0.z*b0.z + a0.w*b0.w
         + a1.x*b1.x + a1.y*b1.y + a1.z*b1.z + a1.w*b1.w;
}

// ---------------------------------------------------------------------------
// Kernel 1: tiny precomputations. One warp per task.
// ---------------------------------------------------------------------------
__global__ void prep_kernel(const float* __restrict__ company_emb,
                            const float* __restrict__ comp_table,
                            const float* __restrict__ W_proj,
                            const float* __restrict__ b_proj,
                            const float* __restrict__ theta,
                            const float* __restrict__ w_ff,
                            const float* __restrict__ w_fc,
                            const float* __restrict__ b_fc,
                            const float* __restrict__ W2,
                            const float* __restrict__ b2,
                            const int*   __restrict__ com_id)
{
    int wt   = (blockIdx.x * blockDim.x + threadIdx.x) >> 5;
    int lane = threadIdx.x & 31;

    if (wt < Dc) {
        float s = warp_sum(dot8(W_proj + (size_t)wt*Dc + lane*8, w_ff + lane*8));
        if (lane == 0) g_u[wt] = s;
    } else if (wt < Dc + Dc/2) {
        int j = wt - Dc;
        float s = warp_sum(dot8(W2 + (size_t)j*Dc + lane*8, w_ff + lane*8));
        if (lane == 0) g_w2v[j] = s;
    } else if (wt < Dc + Dc/2 + Bc) {
        int b   = wt - Dc - Dc/2;
        int cid = com_id[b];
        float th = theta[cid];
        float s = 0.f;
        #pragma unroll
        for (int i = 0; i < 8; i++) {
            int d = lane*8 + i;
            float m = (1.f - th) * company_emb[b*Dc + d] + th * comp_table[(size_t)cid*Dc + d];
            s += m * w_fc[d];
        }
        s = warp_sum(s);
        if (lane == 0) g_comp[b] = s + b_fc[0];
    } else if (wt == Dc + Dc/2 + Bc) {
        float s = warp_sum(dot8(b_proj + lane*8, w_ff + lane*8));
        if (lane == 0) g_c0 = s;
    } else if (wt == Dc + Dc/2 + Bc + 1) {
        float s = warp_sum(dot8(b2 + lane*8, w_ff + lane*8));
        if (lane == 0) g_c2 = s;
    }
}

// ---------------------------------------------------------------------------
// Kernel 2: his-node MLP collapsed to a scalar per his slot.
//   hisdot[i] = leaky(rfe[f] @ W1 + b1) . w2v + c2,  f = his_nodes[i]
// One block (128 threads, thread j owns hidden unit j) per his slot.
// ---------------------------------------------------------------------------
__global__ void his_kernel(const float* __restrict__ raw_field_embed,
                           const float* __restrict__ W1,
                           const float* __restrict__ b1,
                           const int*   __restrict__ his_nodes)
{
    __shared__ __align__(16) float rfe[Dc];
    __shared__ float red[4];
    int f = his_nodes[blockIdx.x];
    int t = threadIdx.x; // 0..127
    rfe[t]       = raw_field_embed[(size_t)f*Dc + t];
    rfe[t + 128] = raw_field_embed[(size_t)f*Dc + t + 128];
    __syncthreads();

    float acc = b1[t];
    #pragma unroll 8
    for (int k = 0; k < Dc; k++)
        acc += rfe[k] * W1[(size_t)k*(Dc/2) + t];   // coalesced across t
    float y = (acc >= 0.f) ? acc : 0.01f * acc;
    float p = y * g_w2v[t];

    p = warp_sum(p);
    if ((t & 31) == 0) red[t >> 5] = p;
    __syncthreads();
    if (t == 0)
        g_hisdot[blockIdx.x] = red[0] + red[1] + red[2] + red[3] + g_c2;
}

// ---------------------------------------------------------------------------
// Kernel 3: dense pass (streams field_table once).
//   out[b,f] = field_table[f] . u + c0 + b_ff + comp[b]
// One warp per field row; lanes 0..3 write the 4 batch rows.
// ---------------------------------------------------------------------------
__global__ void __launch_bounds__(256) main_kernel(const float* __restrict__ field_table,
                                                   const float* __restrict__ b_ff,
                                                   float* __restrict__ out)
{
    __shared__ __align__(16) float u_s[Dc];
    __shared__ float add_s[Bc];
    int t = threadIdx.x;
    u_s[t] = g_u[t];
    if (t < Bc) add_s[t] = g_comp[t] + b_ff[0] + g_c0;
    __syncthreads();

    int warp = t >> 5, lane = t & 31;
    int f = blockIdx.x * 8 + warp;
    if (f >= Fc) return;

    float s = dot8(field_table + (size_t)f*Dc + lane*8, u_s + lane*8);
    s = warp_sum(s); // all lanes have it
    if (lane < Bc) out[(size_t)lane*Fc + f] = s + add_s[lane];
}

// ---------------------------------------------------------------------------
// Kernel 4: sparse corrections — now fully parallel.
// grid = (24, Bc): blockIdx.y = batch, 8 warps/block, ONE node per warp
// (24 blocks x 8 warps = 192 nodes = KN + KH). Overwrites touched rows
// with the full value (set semantics; duplicates write identical bits).
// ---------------------------------------------------------------------------
__global__ void __launch_bounds__(256) corr_kernel(
                            const float* __restrict__ field_table,
                            const float* __restrict__ field_emb,
                            const float* __restrict__ alpha_fields,
                            const float* __restrict__ w_ff,
                            const float* __restrict__ b_ff,
                            const int*   __restrict__ now_nodes,
                            const int*   __restrict__ his_nodes,
                            float* __restrict__ out)
{
    __shared__ __align__(16) float u_s[Dc];
    __shared__ __align__(16) float wff_s[Dc];
    __shared__ int now_s[KNc], his_s[KHc];
    int b = blockIdx.y;
    int t = threadIdx.x; // 256
    u_s[t]   = g_u[t];
    wff_s[t] = w_ff[t];
    if (t < KNc) now_s[t] = now_nodes[b*KNc + t];
    if (t < KHc) his_s[t] = his_nodes[b*KHc + t];
    __syncthreads();

    float cb = g_comp[b] + b_ff[0];
    float c0 = g_c0;
    int warp = t >> 5, lane = t & 31;

    int node = blockIdx.x * 8 + warp;            // 0 .. 191
    int f = (node < KNc) ? now_s[node] : his_s[node - KNc];

    // Two independent 1KB row gathers -> MLP=4 per lane; overlapped chip-wide
    // across ~768 warps instead of serialized in 4 blocks.
    float a1 = dot8(field_table + (size_t)f*Dc + lane*8, u_s   + lane*8);
    float a2 = dot8(field_emb   + (size_t)f*Dc + lane*8, wff_s + lane*8);
    a1 = warp_sum(a1);   // base_dot (without c0)
    a2 = warp_sum(a2);   // now-term dot

    // membership: now (64 entries, 2/lane)
    bool inNow = (now_s[lane] == f) || (now_s[lane + 32] == f);
    unsigned mN = __ballot_sync(0xffffffffu, inNow);

    // membership + first matching slot in his (128 entries, 4/lane)
    int jmin = INT_MAX;
    #pragma unroll
    for (int r = 0; r < 4; r++) {
        int j = lane + r*32;
        if (his_s[j] == f && j < jmin) jmin = j;
    }
    #pragma unroll
    for (int o = 16; o > 0; o >>= 1) {
        int oth = __shfl_xor_sync(0xffffffffu, jmin, o);
        jmin = min(jmin, oth);
    }

    float alpha = alpha_fields[f];
    float val = (1.f - alpha) * (a1 + c0) + cb;
    if (mN)              val += alpha * a2;
    if (jmin != INT_MAX) val += alpha * g_hisdot[b*KHc + jmin];

    if (lane == 0) out[(size_t)b*Fc + f] = val;
}

// ---------------------------------------------------------------------------
extern "C" void kernel_launch(void* const* d_in, const int* in_sizes, int n_in,
                              void* d_out, int out_size)
{
    const float* company_emb     = (const float*)d_in[0];
    const float* field_emb       = (const float*)d_in[1];
    const float* raw_field_embed = (const float*)d_in[2];
    const float* comp_table      = (const float*)d_in[3];
    const float* field_table     = (const float*)d_in[4];
    const float* W_proj          = (const float*)d_in[5];
    const float* b_proj          = (const float*)d_in[6];
    const float* theta           = (const float*)d_in[7];
    const float* alpha_fields    = (const float*)d_in[8];
    const float* w_ff            = (const float*)d_in[9];
    const float* b_ff            = (const float*)d_in[10];
    const float* w_fc            = (const float*)d_in[11];
    const float* b_fc            = (const float*)d_in[12];
    const float* W1              = (const float*)d_in[13];
    const float* b1              = (const float*)d_in[14];
    const float* W2              = (const float*)d_in[15];
    const float* b2              = (const float*)d_in[16];
    const int*   now_nodes       = (const int*)d_in[17];
    const int*   his_nodes       = (const int*)d_in[18];
    const int*   com_id          = (const int*)d_in[19];
    float* out = (float*)d_out;

    // 390 warp-tasks -> 49 blocks of 8 warps
    prep_kernel<<<49, 256>>>(company_emb, comp_table, W_proj, b_proj, theta,
                             w_ff, w_fc, b_fc, W2, b2, com_id);
    his_kernel<<<Bc*KHc, 128>>>(raw_field_embed, W1, b1, his_nodes);
    main_kernel<<<(Fc + 7) / 8, 256>>>(field_table, b_ff, out);
    dim3 cgrid((KNc + KHc) / 8, Bc);
    corr_kernel<<<cgrid, 256>>>(field_table, field_emb, alpha_fields, w_ff, b_ff,
                                now_nodes, his_nodes, out);
}